// round 15
// baseline (speedup 1.0000x reference)
#include <cuda_runtime.h>
#include <math_constants.h>

#define NN 10000
#define BB 4
#define EE 160000
#define CC 64
#define CE 16
#define NR (NN*BB)          // 40000 rows
#define XSTRIDE 68          // padded row stride for transposed activation tiles

// Node tensors g_aggr/shared staging use INTERLEAVED layout: channel c -> p =
// ilv(c) = (c&31)*2 + (c>>5). xp1/xp2 use PACKED layout: value (node n, batch
// b, interleaved-p) at n*256 + (p>>1)*8 + b*2 + (p&1)  -> aggr reads 2xLDG.128.
__device__ float  g_xp1[NR*CC];
__device__ float  g_xp2[NR*CC];
__device__ float  g_aggr[NR*CC];
__device__ float  g_asrc1[NR], g_adst1[NR];
__device__ float  g_asrc2[NR], g_adst2[NR];
__device__ float  g_qaw[2][CC], g_kaw[2][CC], g_wea[2][CE];
__device__ float  g_abv[2];
__device__ int  g_deg[NN];           // zeroed at END of each run (and statically)
__device__ int  g_off[NN+1];
__device__ int  g_cur[NN];
// 80-byte CSR edge record: [0]={bitcast src, esc1, esc2, pad}, [1..4]=eattr
__device__ float4 g_recs[EE*5];

__device__ __forceinline__ float sigmoidf(float x) {
    return 1.0f / (1.0f + __expf(-x));
}
__device__ __forceinline__ int ilv(int c)   { return (c & 31) * 2 + (c >> 5); }
__device__ __forceinline__ int unilv(int p) { return (p >> 1) + (p & 1) * 32; }

// ---------------- launch 0: fold attention weights + degree count ----------
__global__ void prep_count_kernel(const int* __restrict__ ei,
                                  const float* q1, const float* k1, const float* aw1,
                                  const float* ab1, const float* we1,
                                  const float* q2, const float* k2, const float* aw2,
                                  const float* ab2, const float* we2) {
    int tid = threadIdx.x;
    if (blockIdx.x < 2) {
        int layer = blockIdx.x;
        const float* q  = layer ? q2  : q1;
        const float* k  = layer ? k2  : k1;
        const float* aw = layer ? aw2 : aw1;
        const float* ab = layer ? ab2 : ab1;
        const float* we = layer ? we2 : we1;
        int w = tid >> 5, lane = tid & 31;
        float awq_lo = aw[lane],        awq_hi = aw[32 + lane];
        float awk_lo = aw[64 + lane],   awk_hi = aw[96 + lane];
        float aw3_lo = aw[128 + lane],  aw3_hi = aw[160 + lane];
        #pragma unroll
        for (int i = 0; i < 8; i++) {
            int row = w * 8 + i;
            float sq = q[row*CC + lane] * awq_lo + q[row*CC + 32 + lane] * awq_hi;
            float sk = k[row*CC + lane] * awk_lo + k[row*CC + 32 + lane] * awk_hi;
            #pragma unroll
            for (int o = 16; o; o >>= 1) {
                sq += __shfl_down_sync(0xffffffffu, sq, o);
                sk += __shfl_down_sync(0xffffffffu, sk, o);
            }
            if (lane == 0) { g_qaw[layer][row] = sq; g_kaw[layer][row] = sk; }
        }
        #pragma unroll
        for (int i = 0; i < 2; i++) {
            int row = w * 2 + i;
            float s = we[row*CC + lane] * aw3_lo + we[row*CC + 32 + lane] * aw3_hi;
            #pragma unroll
            for (int o = 16; o; o >>= 1) s += __shfl_down_sync(0xffffffffu, s, o);
            if (lane == 0) g_wea[layer][row] = s;
        }
        if (tid == 0) g_abv[layer] = ab[0];
    }
    int e = blockIdx.x * 256 + tid;   // 625*256 = 160000 exactly
    atomicAdd(&g_deg[ei[EE + e]], 1);
}

// ---------------- launch 1: exclusive scan -> g_off / g_cur ----------------
__global__ void scan_kernel() {
    __shared__ int s[1024];
    const int CH = (NN + 1023) / 1024;
    int t = threadIdx.x;
    int base = t * CH;
    int local[CH];
    int sum = 0;
    #pragma unroll
    for (int i = 0; i < CH; i++) {
        local[i] = sum;
        if (base + i < NN) sum += g_deg[base + i];
    }
    s[t] = sum;
    __syncthreads();
    for (int off = 1; off < 1024; off <<= 1) {
        int v = (t >= off) ? s[t - off] : 0;
        __syncthreads();
        s[t] += v;
        __syncthreads();
    }
    int excl = (t == 0) ? 0 : s[t - 1];
    #pragma unroll
    for (int i = 0; i < CH; i++) {
        if (base + i < NN) {
            int o = excl + local[i];
            g_off[base + i] = o;
            g_cur[base + i] = o;
        }
    }
    if (t == 1023) g_off[NN] = s[1023];
}

// ---------------- launch 2: xform1 GEMM + scatter(wide rec) + escal --------
__global__ void xform1_scatter_kernel(const float* __restrict__ x,
                                      const float* __restrict__ wn,
                                      const int* __restrict__ ei,
                                      const float* __restrict__ eattr) {
    __shared__ __align__(16) float ws[CC*CC];         // [k][interleaved c]
    __shared__ __align__(16) float xs_t[CC*XSTRIDE];  // [k][row]
    __shared__ float qs[CC], ks_[CC];
    __shared__ float redq[64], redk[64];
    __shared__ float w1[CE], w2[CE];
    __shared__ float ab0, ab1;
    int tid = threadIdx.x;
    for (int i = tid; i < CC*CC; i += 256) {
        int kk = i >> 6, c = i & 63;
        ws[kk*CC + ilv(c)] = wn[i];
    }
    if (tid < CC) { qs[tid] = g_qaw[0][unilv(tid)]; ks_[tid] = g_kaw[0][unilv(tid)]; }
    if (tid >= 64 && tid < 64 + CE) { w1[tid-64] = g_wea[0][tid-64]; w2[tid-64] = g_wea[1][tid-64]; }
    if (tid == 127) { ab0 = g_abv[0]; ab1 = g_abv[1]; }
    int row0 = blockIdx.x * 64;
    for (int i = tid*4; i < 64*CC; i += 1024) {
        float4 v = *(const float4*)&x[row0*CC + i];
        int r = i >> 6, c0 = i & 63;
        xs_t[(c0+0)*XSTRIDE + r] = v.x;
        xs_t[(c0+1)*XSTRIDE + r] = v.y;
        xs_t[(c0+2)*XSTRIDE + r] = v.z;
        xs_t[(c0+3)*XSTRIDE + r] = v.w;
    }
    __syncthreads();
    // ---- scatter wide record + escal (both layers) for 256 edges ----
    {
        int e = blockIdx.x * 256 + tid;
        int src = ei[e];
        int dst = ei[EE + e];
        int pos = atomicAdd(&g_cur[dst], 1);
        const float4* p = (const float4*)(eattr + (size_t)e * CE);
        float4 A = p[0], B = p[1], C = p[2], D = p[3];
        float a[16] = {A.x,A.y,A.z,A.w, B.x,B.y,B.z,B.w, C.x,C.y,C.z,C.w, D.x,D.y,D.z,D.w};
        float s1 = 0.f, s2 = 0.f;
        #pragma unroll
        for (int j = 0; j < CE; j++) { s1 += a[j]*w1[j]; s2 += a[j]*w2[j]; }
        float4* rec = &g_recs[(size_t)pos * 5];
        rec[0] = make_float4(__int_as_float(src), s1 + ab0, s2 + ab1, 0.f);
        rec[1] = A; rec[2] = B; rec[3] = C; rec[4] = D;
    }
    // ---- register-tiled GEMM: 64 rows x 64 cols ----
    int tc = tid & 15, tg = tid >> 4;
    int r0 = tg * 4;                  // node-aligned: rows r0..r0+3 = one node
    float acc[4][4] = {};
    #pragma unroll 16
    for (int kk = 0; kk < CC; kk++) {
        float4 w = *(float4*)&ws[kk*CC + tc*4];
        float4 a = *(float4*)&xs_t[kk*XSTRIDE + r0];
        acc[0][0]+=a.x*w.x; acc[0][1]+=a.x*w.y; acc[0][2]+=a.x*w.z; acc[0][3]+=a.x*w.w;
        acc[1][0]+=a.y*w.x; acc[1][1]+=a.y*w.y; acc[1][2]+=a.y*w.z; acc[1][3]+=a.y*w.w;
        acc[2][0]+=a.z*w.x; acc[2][1]+=a.z*w.y; acc[2][2]+=a.z*w.z; acc[2][3]+=a.z*w.w;
        acc[3][0]+=a.w*w.x; acc[3][1]+=a.w*w.y; acc[3][2]+=a.w*w.z; acc[3][3]+=a.w*w.w;
    }
    // packed xp1 write: node = row0/4 + tg
    {
        int node = (row0 >> 2) + tg;
        int l0 = tc * 2;
        float* base = &g_xp1[node*256 + l0*8];
        *(float4*)(base + 0)  = make_float4(acc[0][0], acc[0][1], acc[1][0], acc[1][1]);
        *(float4*)(base + 4)  = make_float4(acc[2][0], acc[2][1], acc[3][0], acc[3][1]);
        *(float4*)(base + 8)  = make_float4(acc[0][2], acc[0][3], acc[1][2], acc[1][3]);
        *(float4*)(base + 12) = make_float4(acc[2][2], acc[2][3], acc[3][2], acc[3][3]);
    }
    float4 qv = *(float4*)&qs[tc*4];
    float4 kv = *(float4*)&ks_[tc*4];
    #pragma unroll
    for (int i = 0; i < 4; i++) {
        float pq = acc[i][0]*qv.x + acc[i][1]*qv.y + acc[i][2]*qv.z + acc[i][3]*qv.w;
        float pk = acc[i][0]*kv.x + acc[i][1]*kv.y + acc[i][2]*kv.z + acc[i][3]*kv.w;
        #pragma unroll
        for (int o = 8; o; o >>= 1) {
            pq += __shfl_down_sync(0xffffffffu, pq, o, 16);
            pk += __shfl_down_sync(0xffffffffu, pk, o, 16);
        }
        if (tc == 0) { redq[tg*4 + i] = pq; redk[tg*4 + i] = pk; }
    }
    __syncthreads();
    if (tid < 64) {
        g_asrc1[row0 + tid] = redq[tid];
        g_adst1[row0 + tid] = redk[tid];
    }
}

// ---------------- launch 3 (PROBE) / 5: segment max, sequential edge stream -
// block = 256 = 8 warps = 4 nodes x 2 half-warps (contiguous halves, R11 shape)
__global__ void __launch_bounds__(256, 4)
aggr_kernel(const float* __restrict__ xp, const float* __restrict__ asrcp,
            const float* __restrict__ adstp, float* __restrict__ aggrp,
            const float* __restrict__ we, int layer) {
    __shared__ __align__(16) float4 wsh4[(CE/2)*32];   // [j/2][lane], 4KB
    __shared__ float2 part[4][BB][32];
    int tid = threadIdx.x;
    int lane = tid & 31;
    int w = tid >> 5;
    int nloc = w >> 1, half = w & 1;
    int lb = lane & 3;
    for (int i = tid; i < (CE/2)*32; i += 256) {
        int j2 = i >> 5, l = i & 31;
        wsh4[i] = make_float4(we[(2*j2)*CC + l],   we[(2*j2)*CC + 32 + l],
                              we[(2*j2+1)*CC + l], we[(2*j2+1)*CC + 32 + l]);
    }
    __syncthreads();
    int n = blockIdx.x * 4 + nloc;
    int beg0 = g_off[n], end0 = g_off[n+1];
    int mid = beg0 + ((end0 - beg0) >> 1);
    int beg = half ? mid : beg0;
    int end = half ? end0 : mid;
    float ad_l = adstp[n*4 + lb];
    float mx0[BB], mx1[BB];
    #pragma unroll
    for (int b = 0; b < BB; b++) { mx0[b] = -CUDART_INF_F; mx1[b] = -CUDART_INF_F; }
    // prefetch header of first record (address computable, no chase)
    float4 nr = (beg < end) ? __ldg(&g_recs[(size_t)beg * 5]) : make_float4(0.f,0.f,0.f,0.f);
    for (int i = beg; i < end; i++) {
        float4 r0 = nr;
        if (i + 1 < end) nr = __ldg(&g_recs[(size_t)(i+1) * 5]);
        int src = __float_as_int(r0.x);
        float esc = layer ? r0.z : r0.y;
        const float4* rec = &g_recs[(size_t)i * 5];
        float4 A = __ldg(&rec[1]);
        float4 B = __ldg(&rec[2]);
        float4 C = __ldg(&rec[3]);
        float4 D = __ldg(&rec[4]);
        float att_l = sigmoidf(__ldg(&asrcp[src*4 + lb]) + ad_l + esc);
        float attv[BB];
        #pragma unroll
        for (int b = 0; b < BB; b++) attv[b] = __shfl_sync(0xffffffffu, att_l, b, 4);
        float gx = 0.f, gy = 0.f;
        {
            float4 w0 = wsh4[0*32 + lane], w1 = wsh4[1*32 + lane];
            gx += A.x*w0.x + A.y*w0.z + A.z*w1.x + A.w*w1.z;
            gy += A.x*w0.y + A.y*w0.w + A.z*w1.y + A.w*w1.w;
        }
        {
            float4 w0 = wsh4[2*32 + lane], w1 = wsh4[3*32 + lane];
            gx += B.x*w0.x + B.y*w0.z + B.z*w1.x + B.w*w1.z;
            gy += B.x*w0.y + B.y*w0.w + B.z*w1.y + B.w*w1.w;
        }
        {
            float4 w0 = wsh4[4*32 + lane], w1 = wsh4[5*32 + lane];
            gx += C.x*w0.x + C.y*w0.z + C.z*w1.x + C.w*w1.z;
            gy += C.x*w0.y + C.y*w0.w + C.z*w1.y + C.w*w1.w;
        }
        {
            float4 w0 = wsh4[6*32 + lane], w1 = wsh4[7*32 + lane];
            gx += D.x*w0.x + D.y*w0.z + D.z*w1.x + D.w*w1.z;
            gy += D.x*w0.y + D.y*w0.w + D.z*w1.y + D.w*w1.w;
        }
        float gA = sigmoidf(gx), gB = sigmoidf(gy);
        const float* xb = &xp[src*256 + lane*8];
        float4 f1 = *(const float4*)(xb);       // b0q0 b0q1 b1q0 b1q1
        float4 f2 = *(const float4*)(xb + 4);   // b2q0 b2q1 b3q0 b3q1
        mx0[0] = fmaxf(mx0[0], attv[0] * f1.x * gA);
        mx1[0] = fmaxf(mx1[0], attv[0] * f1.y * gB);
        mx0[1] = fmaxf(mx0[1], attv[1] * f1.z * gA);
        mx1[1] = fmaxf(mx1[1], attv[1] * f1.w * gB);
        mx0[2] = fmaxf(mx0[2], attv[2] * f2.x * gA);
        mx1[2] = fmaxf(mx1[2], attv[2] * f2.y * gB);
        mx0[3] = fmaxf(mx0[3], attv[3] * f2.z * gA);
        mx1[3] = fmaxf(mx1[3], attv[3] * f2.w * gB);
    }
    if (half == 1) {
        #pragma unroll
        for (int b = 0; b < BB; b++) part[nloc][b][lane] = make_float2(mx0[b], mx1[b]);
    }
    __syncthreads();
    if (half == 0) {
        bool empty = (beg0 == end0);
        #pragma unroll
        for (int b = 0; b < BB; b++) {
            float2 p1 = part[nloc][b][lane];
            float2 o = empty ? make_float2(0.f, 0.f)
                             : make_float2(fmaxf(mx0[b], p1.x), fmaxf(mx1[b], p1.y));
            *(float2*)&aggrp[(n*BB + b)*CC + lane*2] = o;
        }
    }
}

// ---------------- launch 4: layer1 output + layer2 transform (67 KB) -------
__global__ void mid_kernel(const float* __restrict__ ow, const float* __restrict__ ob,
                           const float* __restrict__ wn2) {
    extern __shared__ __align__(16) float sm[];
    float* ows  = sm;                  // 2*CC*CC
    float* xs_t = ows + 2*CC*CC;       // CC*XSTRIDE (xp1, later ys)
    float* as_t = xs_t + CC*XSTRIDE;   // CC*XSTRIDE (aggr, later wn2)
    __shared__ float obi[CC], qs[CC], ks_[CC];
    __shared__ float redq[64], redk[64];
    int tid = threadIdx.x;
    for (int i = tid; i < 2*CC*CC; i += 256) {
        int k = i >> 6, c = i & 63;
        int pk = (k < CC) ? ilv(k) : CC + ilv(k - CC);
        ows[pk*CC + ilv(c)] = ow[i];
    }
    if (tid < CC) {
        int c = unilv(tid);
        obi[tid] = ob[c];
        qs[tid]  = g_qaw[1][c];
        ks_[tid] = g_kaw[1][c];
    }
    int row0 = blockIdx.x * 64;
    size_t nbase = (size_t)row0 * CC;   // == node0*256
    for (int i = tid*4; i < 64*CC; i += 1024) {
        {
            float4 v = *(const float4*)&g_xp1[nbase + i];
            int np = i >> 8, l = (i & 255) >> 3, s = (i >> 2) & 1;
            int rb = np*4 + 2*s;
            int p0 = 2*l, p1 = 2*l + 1;
            xs_t[p0*XSTRIDE + rb]     = v.x;
            xs_t[p1*XSTRIDE + rb]     = v.y;
            xs_t[p0*XSTRIDE + rb + 1] = v.z;
            xs_t[p1*XSTRIDE + rb + 1] = v.w;
        }
        {
            float4 u = *(const float4*)&g_aggr[nbase + i];
            int r = i >> 6, p0 = i & 63;
            as_t[(p0+0)*XSTRIDE + r] = u.x;
            as_t[(p0+1)*XSTRIDE + r] = u.y;
            as_t[(p0+2)*XSTRIDE + r] = u.z;
            as_t[(p0+3)*XSTRIDE + r] = u.w;
        }
    }
    __syncthreads();
    int tc = tid & 15, tg = tid >> 4;
    int r0 = tg * 4;
    float acc[4][4];
    {
        float4 bv = *(float4*)&obi[tc*4];
        #pragma unroll
        for (int i = 0; i < 4; i++) { acc[i][0]=bv.x; acc[i][1]=bv.y; acc[i][2]=bv.z; acc[i][3]=bv.w; }
    }
    #pragma unroll 16
    for (int kk = 0; kk < CC; kk++) {
        float4 w = *(float4*)&ows[kk*CC + tc*4];
        float4 a = *(float4*)&xs_t[kk*XSTRIDE + r0];
        acc[0][0]+=a.x*w.x; acc[0][1]+=a.x*w.y; acc[0][2]+=a.x*w.z; acc[0][3]+=a.x*w.w;
        acc[1][0]+=a.y*w.x; acc[1][1]+=a.y*w.y; acc[1][2]+=a.y*w.z; acc[1][3]+=a.y*w.w;
        acc[2][0]+=a.z*w.x; acc[2][1]+=a.z*w.y; acc[2][2]+=a.z*w.z; acc[2][3]+=a.z*w.w;
        acc[3][0]+=a.w*w.x; acc[3][1]+=a.w*w.y; acc[3][2]+=a.w*w.z; acc[3][3]+=a.w*w.w;
    }
    #pragma unroll 16
    for (int kk = 0; kk < CC; kk++) {
        float4 w = *(float4*)&ows[(CC+kk)*CC + tc*4];
        float4 a = *(float4*)&as_t[kk*XSTRIDE + r0];
        acc[0][0]+=a.x*w.x; acc[0][1]+=a.x*w.y; acc[0][2]+=a.x*w.z; acc[0][3]+=a.x*w.w;
        acc[1][0]+=a.y*w.x; acc[1][1]+=a.y*w.y; acc[1][2]+=a.y*w.z; acc[1][3]+=a.y*w.w;
        acc[2][0]+=a.z*w.x; acc[2][1]+=a.z*w.y; acc[2][2]+=a.z*w.z; acc[2][3]+=a.z*w.w;
        acc[3][0]+=a.w*w.x; acc[3][1]+=a.w*w.y; acc[3][2]+=a.w*w.z; acc[3][3]+=a.w*w.w;
    }
    __syncthreads();   // everyone done READING as_t/xs_t for phase 1+2
    // ys -> xs_t in place; wn2 -> as_t region
    #pragma unroll
    for (int i = 0; i < 4; i++) {
        #pragma unroll
        for (int j = 0; j < 4; j++) {
            int p = tc*4 + j, r = r0 + i;
            float v = xs_t[p*XSTRIDE + r] + acc[i][j];
            xs_t[p*XSTRIDE + r] = (v > 0.f) ? v : 0.01f * v;
        }
    }
    for (int i = tid; i < CC*CC; i += 256) {
        int k = i >> 6, c = i & 63;
        as_t[ilv(k)*CC + ilv(c)] = wn2[i];   // reuse as_t as [k][c] weight tile
    }
    __syncthreads();
    float acc2[4][4] = {};
    #pragma unroll 16
    for (int kk = 0; kk < CC; kk++) {
        float4 w = *(float4*)&as_t[kk*CC + tc*4];
        float4 a = *(float4*)&xs_t[kk*XSTRIDE + r0];
        acc2[0][0]+=a.x*w.x; acc2[0][1]+=a.x*w.y; acc2[0][2]+=a.x*w.z; acc2[0][3]+=a.x*w.w;
        acc2[1][0]+=a.y*w.x; acc2[1][1]+=a.y*w.y; acc2[1][2]+=a.y*w.z; acc2[1][3]+=a.y*w.w;
        acc2[2][0]+=a.z*w.x; acc2[2][1]+=a.z*w.y; acc2[2][2]+=a.z*w.z; acc2[2][3]+=a.z*w.w;
        acc2[3][0]+=a.w*w.x; acc2[3][1]+=a.w*w.y; acc2[3][2]+=a.w*w.z; acc2[3][3]+=a.w*w.w;
    }
    // packed xp2 write
    {
        int node = (row0 >> 2) + tg;
        int l0 = tc * 2;
        float* base = &g_xp2[node*256 + l0*8];
        *(float4*)(base + 0)  = make_float4(acc2[0][0], acc2[0][1], acc2[1][0], acc2[1][1]);
        *(float4*)(base + 4)  = make_float4(acc2[2][0], acc2[2][1], acc2[3][0], acc2[3][1]);
        *(float4*)(base + 8)  = make_float4(acc2[0][2], acc2[0][3], acc2[1][2], acc2[1][3]);
        *(float4*)(base + 12) = make_float4(acc2[2][2], acc2[2][3], acc2[3][2], acc2[3][3]);
    }
    float4 qv = *(float4*)&qs[tc*4];
    float4 kv = *(float4*)&ks_[tc*4];
    #pragma unroll
    for (int i = 0; i < 4; i++) {
        float pq = acc2[i][0]*qv.x + acc2[i][1]*qv.y + acc2[i][2]*qv.z + acc2[i][3]*qv.w;
        float pk = acc2[i][0]*kv.x + acc2[i][1]*kv.y + acc2[i][2]*kv.z + acc2[i][3]*kv.w;
        #pragma unroll
        for (int o = 8; o; o >>= 1) {
            pq += __shfl_down_sync(0xffffffffu, pq, o, 16);
            pk += __shfl_down_sync(0xffffffffu, pk, o, 16);
        }
        if (tc == 0) { redq[tg*4 + i] = pq; redk[tg*4 + i] = pk; }
    }
    __syncthreads();
    if (tid < 64) {
        g_asrc2[row0 + tid] = redq[tid];
        g_adst2[row0 + tid] = redk[tid];
    }
}

// ---------------- launch 6: final output + re-zero degrees -----------------
__global__ void out2_kernel(const float* __restrict__ ow, const float* __restrict__ ob,
                            float* __restrict__ yout) {
    extern __shared__ __align__(16) float sm[];
    float* ows  = sm;
    float* xs_t = ows + 2*CC*CC;
    float* as_t = xs_t + CC*XSTRIDE;
    __shared__ float obi[CC];
    int tid = threadIdx.x;
    if (blockIdx.x < 40) {
        int i = blockIdx.x * 256 + tid;
        if (i < NN) g_deg[i] = 0;
    }
    for (int i = tid; i < 2*CC*CC; i += 256) {
        int k = i >> 6, c = i & 63;
        int pk = (k < CC) ? ilv(k) : CC + ilv(k - CC);
        ows[pk*CC + ilv(c)] = ow[i];
    }
    if (tid < CC) obi[tid] = ob[unilv(tid)];
    int row0 = blockIdx.x * 64;
    size_t nbase = (size_t)row0 * CC;
    for (int i = tid*4; i < 64*CC; i += 1024) {
        {   // xp2 packed
            float4 v = *(const float4*)&g_xp2[nbase + i];
            int np = i >> 8, l = (i & 255) >> 3, s = (i >> 2) & 1;
            int rb = np*4 + 2*s;
            int p0 = 2*l, p1 = 2*l + 1;
            xs_t[p0*XSTRIDE + rb]     = v.x;
            xs_t[p1*XSTRIDE + rb]     = v.y;
            xs_t[p0*XSTRIDE + rb + 1] = v.z;
            xs_t[p1*XSTRIDE + rb + 1] = v.w;
        }
        {   // aggr interleaved
            float4 u = *(const float4*)&g_aggr[nbase + i];
            int r = i >> 6, p0 = i & 63;
            as_t[(p0+0)*XSTRIDE + r] = u.x;
            as_t[(p0+1)*XSTRIDE + r] = u.y;
            as_t[(p0+2)*XSTRIDE + r] = u.z;
            as_t[(p0+3)*XSTRIDE + r] = u.w;
        }
    }
    __syncthreads();
    int tc = tid & 15, tg = tid >> 4;
    int r0 = tg * 4;
    float acc[4][4];
    {
        float4 bv = *(float4*)&obi[tc*4];
        #pragma unroll
        for (int i = 0; i < 4; i++) { acc[i][0]=bv.x; acc[i][1]=bv.y; acc[i][2]=bv.z; acc[i][3]=bv.w; }
    }
    #pragma unroll 16
    for (int kk = 0; kk < CC; kk++) {
        float4 w = *(float4*)&ows[kk*CC + tc*4];
        float4 a = *(float4*)&xs_t[kk*XSTRIDE + r0];
        acc[0][0]+=a.x*w.x; acc[0][1]+=a.x*w.y; acc[0][2]+=a.x*w.z; acc[0][3]+=a.x*w.w;
        acc[1][0]+=a.y*w.x; acc[1][1]+=a.y*w.y; acc[1][2]+=a.y*w.z; acc[1][3]+=a.y*w.w;
        acc[2][0]+=a.z*w.x; acc[2][1]+=a.z*w.y; acc[2][2]+=a.z*w.z; acc[2][3]+=a.z*w.w;
        acc[3][0]+=a.w*w.x; acc[3][1]+=a.w*w.y; acc[3][2]+=a.w*w.z; acc[3][3]+=a.w*w.w;
    }
    #pragma unroll 16
    for (int kk = 0; kk < CC; kk++) {
        float4 w = *(float4*)&ows[(CC+kk)*CC + tc*4];
        float4 a = *(float4*)&as_t[kk*XSTRIDE + r0];
        acc[0][0]+=a.x*w.x; acc[0][1]+=a.x*w.y; acc[0][2]+=a.x*w.z; acc[0][3]+=a.x*w.w;
        acc[1][0]+=a.y*w.x; acc[1][1]+=a.y*w.y; acc[1][2]+=a.y*w.z; acc[1][3]+=a.y*w.w;
        acc[2][0]+=a.z*w.x; acc[2][1]+=a.z*w.y; acc[2][2]+=a.z*w.z; acc[2][3]+=a.z*w.w;
        acc[3][0]+=a.w*w.x; acc[3][1]+=a.w*w.y; acc[3][2]+=a.w*w.z; acc[3][3]+=a.w*w.w;
    }
    #pragma unroll
    for (int i = 0; i < 4; i++) {
        int row = row0 + r0 + i;
        #pragma unroll
        for (int j = 0; j < 4; j++) {
            int p = tc*4 + j;
            float v = xs_t[p*XSTRIDE + (r0+i)] + acc[i][j];
            yout[row*CC + unilv(p)] = (v > 0.f) ? v : 0.01f * v;
        }
    }
}

// ---------------- host orchestration ----------------------------------------
extern "C" void kernel_launch(void* const* d_in, const int* in_sizes, int n_in,
                              void* d_out, int out_size) {
    const float* X   = (const float*)d_in[0];
    const int*   ei  = (const int*)  d_in[1];
    const float* ea  = (const float*)d_in[2];
    const float* wn1 = (const float*)d_in[3];
    const float* we1 = (const float*)d_in[4];
    const float* q1  = (const float*)d_in[5];
    const float* k1  = (const float*)d_in[6];
    const float* aw1 = (const float*)d_in[7];
    const float* ab1 = (const float*)d_in[8];
    const float* ow1 = (const float*)d_in[9];
    const float* ob1 = (const float*)d_in[10];
    const float* wn2 = (const float*)d_in[11];
    const float* we2 = (const float*)d_in[12];
    const float* q2  = (const float*)d_in[13];
    const float* k2  = (const float*)d_in[14];
    const float* aw2 = (const float*)d_in[15];
    const float* ab2 = (const float*)d_in[16];
    const float* ow2 = (const float*)d_in[17];
    const float* ob2 = (const float*)d_in[18];

    float *xp1, *xp2, *asrc1, *adst1, *asrc2, *adst2, *aggr;
    cudaGetSymbolAddress((void**)&xp1,   g_xp1);
    cudaGetSymbolAddress((void**)&xp2,   g_xp2);
    cudaGetSymbolAddress((void**)&asrc1, g_asrc1);
    cudaGetSymbolAddress((void**)&adst1, g_adst1);
    cudaGetSymbolAddress((void**)&asrc2, g_asrc2);
    cudaGetSymbolAddress((void**)&adst2, g_adst2);
    cudaGetSymbolAddress((void**)&aggr,  g_aggr);

    const int MID_SMEM = (2*CC*CC + 2*CC*XSTRIDE) * 4;   // ~67 KB
    const int OUT_SMEM = (2*CC*CC + 2*CC*XSTRIDE) * 4;   // ~67 KB
    static bool attr_done = false;
    if (!attr_done) {
        cudaFuncSetAttribute(mid_kernel,  cudaFuncAttributeMaxDynamicSharedMemorySize, MID_SMEM);
        cudaFuncSetAttribute(out2_kernel, cudaFuncAttributeMaxDynamicSharedMemorySize, OUT_SMEM);
        attr_done = true;
    }

    prep_count_kernel<<<625, 256>>>(ei, q1, k1, aw1, ab1, we1, q2, k2, aw2, ab2, we2); // 0
    scan_kernel<<<1, 1024>>>();                                                        // 1
    xform1_scatter_kernel<<<625, 256>>>(X, wn1, ei, ea);                               // 2
    aggr_kernel<<<NN/4, 256>>>(xp1, asrc1, adst1, aggr, we1, 0);                       // 3 <- probe
    mid_kernel<<<NR/64, 256, MID_SMEM>>>(ow1, ob1, wn2);                               // 4
    aggr_kernel<<<NN/4, 256>>>(xp2, asrc2, adst2, aggr, we2, 1);                       // 5
    out2_kernel<<<NR/64, 256, OUT_SMEM>>>(ow2, ob2, (float*)d_out);                    // 6
}

// round 16
// speedup vs baseline: 1.0457x; 1.0457x over previous
#include <cuda_runtime.h>
#include <math_constants.h>

#define NN 10000
#define BB 4
#define EE 160000
#define CC 64
#define CE 16
#define NR (NN*BB)          // 40000 rows
#define XSTRIDE 68          // padded row stride for transposed activation tiles

// Node tensors g_aggr/shared staging use INTERLEAVED layout: channel c -> p =
// ilv(c) = (c&31)*2 + (c>>5). xp1/xp2 use PACKED layout: value (node n, batch
// b, interleaved-p) at n*256 + (p>>1)*8 + b*2 + (p&1)  -> aggr reads 2xLDG.128.
__device__ float  g_xp1[NR*CC];
__device__ float  g_xp2[NR*CC];
__device__ float  g_aggr[NR*CC];
__device__ float  g_asrc1[NR], g_adst1[NR];
__device__ float  g_asrc2[NR], g_adst2[NR];
__device__ float  g_qaw[2][CC], g_kaw[2][CC], g_wea[2][CE];
__device__ float  g_abv[2];
__device__ float  g_esc1[EE], g_esc2[EE];
__device__ int  g_deg[NN];           // zeroed at END of each run (and statically)
__device__ int  g_off[NN+1];
__device__ int  g_cur[NN];
__device__ int2 g_lst[EE];           // {edge id, src node}

__device__ __forceinline__ float sigmoidf(float x) {
    return 1.0f / (1.0f + __expf(-x));
}
__device__ __forceinline__ int ilv(int c)   { return (c & 31) * 2 + (c >> 5); }
__device__ __forceinline__ int unilv(int p) { return (p >> 1) + (p & 1) * 32; }

// ---------------- launch 0: fold attention weights + degree count ----------
__global__ void prep_count_kernel(const int* __restrict__ ei,
                                  const float* q1, const float* k1, const float* aw1,
                                  const float* ab1, const float* we1,
                                  const float* q2, const float* k2, const float* aw2,
                                  const float* ab2, const float* we2) {
    int tid = threadIdx.x;
    if (blockIdx.x < 2) {
        int layer = blockIdx.x;
        const float* q  = layer ? q2  : q1;
        const float* k  = layer ? k2  : k1;
        const float* aw = layer ? aw2 : aw1;
        const float* ab = layer ? ab2 : ab1;
        const float* we = layer ? we2 : we1;
        int w = tid >> 5, lane = tid & 31;
        float awq_lo = aw[lane],        awq_hi = aw[32 + lane];
        float awk_lo = aw[64 + lane],   awk_hi = aw[96 + lane];
        float aw3_lo = aw[128 + lane],  aw3_hi = aw[160 + lane];
        #pragma unroll
        for (int i = 0; i < 8; i++) {
            int row = w * 8 + i;
            float sq = q[row*CC + lane] * awq_lo + q[row*CC + 32 + lane] * awq_hi;
            float sk = k[row*CC + lane] * awk_lo + k[row*CC + 32 + lane] * awk_hi;
            #pragma unroll
            for (int o = 16; o; o >>= 1) {
                sq += __shfl_down_sync(0xffffffffu, sq, o);
                sk += __shfl_down_sync(0xffffffffu, sk, o);
            }
            if (lane == 0) { g_qaw[layer][row] = sq; g_kaw[layer][row] = sk; }
        }
        #pragma unroll
        for (int i = 0; i < 2; i++) {
            int row = w * 2 + i;
            float s = we[row*CC + lane] * aw3_lo + we[row*CC + 32 + lane] * aw3_hi;
            #pragma unroll
            for (int o = 16; o; o >>= 1) s += __shfl_down_sync(0xffffffffu, s, o);
            if (lane == 0) g_wea[layer][row] = s;
        }
        if (tid == 0) g_abv[layer] = ab[0];
    }
    int e = blockIdx.x * 256 + tid;   // 625*256 = 160000 exactly
    atomicAdd(&g_deg[ei[EE + e]], 1);
}

// ---------------- launch 1: exclusive scan -> g_off / g_cur ----------------
__global__ void scan_kernel() {
    __shared__ int s[1024];
    const int CH = (NN + 1023) / 1024;
    int t = threadIdx.x;
    int base = t * CH;
    int local[CH];
    int sum = 0;
    #pragma unroll
    for (int i = 0; i < CH; i++) {
        local[i] = sum;
        if (base + i < NN) sum += g_deg[base + i];
    }
    s[t] = sum;
    __syncthreads();
    for (int off = 1; off < 1024; off <<= 1) {
        int v = (t >= off) ? s[t - off] : 0;
        __syncthreads();
        s[t] += v;
        __syncthreads();
    }
    int excl = (t == 0) ? 0 : s[t - 1];
    #pragma unroll
    for (int i = 0; i < CH; i++) {
        if (base + i < NN) {
            int o = excl + local[i];
            g_off[base + i] = o;
            g_cur[base + i] = o;
        }
    }
    if (t == 1023) g_off[NN] = s[1023];
}

// ---------------- launch 2: xform1 GEMM + scatter + escal ------------------
__global__ void xform1_scatter_kernel(const float* __restrict__ x,
                                      const float* __restrict__ wn,
                                      const int* __restrict__ ei,
                                      const float* __restrict__ eattr) {
    __shared__ __align__(16) float ws[CC*CC];         // [k][interleaved c]
    __shared__ __align__(16) float xs_t[CC*XSTRIDE];  // [k][row]
    __shared__ float qs[CC], ks_[CC];
    __shared__ float redq[64], redk[64];
    __shared__ float w1[CE], w2[CE];
    __shared__ float ab0, ab1;
    int tid = threadIdx.x;
    for (int i = tid; i < CC*CC; i += 256) {
        int kk = i >> 6, c = i & 63;
        ws[kk*CC + ilv(c)] = wn[i];
    }
    if (tid < CC) { qs[tid] = g_qaw[0][unilv(tid)]; ks_[tid] = g_kaw[0][unilv(tid)]; }
    if (tid >= 64 && tid < 64 + CE) { w1[tid-64] = g_wea[0][tid-64]; w2[tid-64] = g_wea[1][tid-64]; }
    if (tid == 127) { ab0 = g_abv[0]; ab1 = g_abv[1]; }
    int row0 = blockIdx.x * 64;
    for (int i = tid*4; i < 64*CC; i += 1024) {
        float4 v = *(const float4*)&x[row0*CC + i];
        int r = i >> 6, c0 = i & 63;
        xs_t[(c0+0)*XSTRIDE + r] = v.x;
        xs_t[(c0+1)*XSTRIDE + r] = v.y;
        xs_t[(c0+2)*XSTRIDE + r] = v.z;
        xs_t[(c0+3)*XSTRIDE + r] = v.w;
    }
    __syncthreads();
    // ---- scatter + escal (both layers) for this block's 256 edges ----
    {
        int e = blockIdx.x * 256 + tid;
        int src = ei[e];
        int dst = ei[EE + e];
        int pos = atomicAdd(&g_cur[dst], 1);
        g_lst[pos] = make_int2(e, src);
        const float4* p = (const float4*)(eattr + (size_t)e * CE);
        float4 A = p[0], B = p[1], C = p[2], D = p[3];
        float a[16] = {A.x,A.y,A.z,A.w, B.x,B.y,B.z,B.w, C.x,C.y,C.z,C.w, D.x,D.y,D.z,D.w};
        float s1 = 0.f, s2 = 0.f;
        #pragma unroll
        for (int j = 0; j < CE; j++) { s1 += a[j]*w1[j]; s2 += a[j]*w2[j]; }
        g_esc1[e] = s1 + ab0;
        g_esc2[e] = s2 + ab1;
    }
    // ---- register-tiled GEMM: 64 rows x 64 cols ----
    int tc = tid & 15, tg = tid >> 4;
    int r0 = tg * 4;                  // node-aligned: rows r0..r0+3 = one node
    float acc[4][4] = {};
    #pragma unroll 16
    for (int kk = 0; kk < CC; kk++) {
        float4 w = *(float4*)&ws[kk*CC + tc*4];
        float4 a = *(float4*)&xs_t[kk*XSTRIDE + r0];
        acc[0][0]+=a.x*w.x; acc[0][1]+=a.x*w.y; acc[0][2]+=a.x*w.z; acc[0][3]+=a.x*w.w;
        acc[1][0]+=a.y*w.x; acc[1][1]+=a.y*w.y; acc[1][2]+=a.y*w.z; acc[1][3]+=a.y*w.w;
        acc[2][0]+=a.z*w.x; acc[2][1]+=a.z*w.y; acc[2][2]+=a.z*w.z; acc[2][3]+=a.z*w.w;
        acc[3][0]+=a.w*w.x; acc[3][1]+=a.w*w.y; acc[3][2]+=a.w*w.z; acc[3][3]+=a.w*w.w;
    }
    // packed xp1 write: node = row0/4 + tg
    {
        int node = (row0 >> 2) + tg;
        int l0 = tc * 2;
        float* base = &g_xp1[node*256 + l0*8];
        *(float4*)(base + 0)  = make_float4(acc[0][0], acc[0][1], acc[1][0], acc[1][1]);
        *(float4*)(base + 4)  = make_float4(acc[2][0], acc[2][1], acc[3][0], acc[3][1]);
        *(float4*)(base + 8)  = make_float4(acc[0][2], acc[0][3], acc[1][2], acc[1][3]);
        *(float4*)(base + 12) = make_float4(acc[2][2], acc[2][3], acc[3][2], acc[3][3]);
    }
    float4 qv = *(float4*)&qs[tc*4];
    float4 kv = *(float4*)&ks_[tc*4];
    #pragma unroll
    for (int i = 0; i < 4; i++) {
        float pq = acc[i][0]*qv.x + acc[i][1]*qv.y + acc[i][2]*qv.z + acc[i][3]*qv.w;
        float pk = acc[i][0]*kv.x + acc[i][1]*kv.y + acc[i][2]*kv.z + acc[i][3]*kv.w;
        #pragma unroll
        for (int o = 8; o; o >>= 1) {
            pq += __shfl_down_sync(0xffffffffu, pq, o, 16);
            pk += __shfl_down_sync(0xffffffffu, pk, o, 16);
        }
        if (tc == 0) { redq[tg*4 + i] = pq; redk[tg*4 + i] = pk; }
    }
    __syncthreads();
    if (tid < 64) {
        g_asrc1[row0 + tid] = redq[tid];
        g_adst1[row0 + tid] = redk[tid];
    }
}

// ---------------- launch 3 (PROBE) / 5: segment max, inline gate ------------
// block = 256 = 8 warps = 4 nodes x 2 half-warps; gate weights as float4 pairs
__global__ void aggr_kernel(const float* __restrict__ xp, const float* __restrict__ asrcp,
                            const float* __restrict__ adstp, float* __restrict__ aggrp,
                            const float* __restrict__ we, const float* __restrict__ eattr,
                            const float* __restrict__ escp) {
    __shared__ __align__(16) float4 wsh4[(CE/2)*32];   // [j/2][lane], 4KB
    __shared__ float2 part[4][BB][32];
    int tid = threadIdx.x;
    int lane = tid & 31;
    int w = tid >> 5;
    int nloc = w >> 1, half = w & 1;
    int lb = lane & 3;
    for (int i = tid; i < (CE/2)*32; i += 256) {
        int j2 = i >> 5, l = i & 31;
        wsh4[i] = make_float4(we[(2*j2)*CC + l],   we[(2*j2)*CC + 32 + l],
                              we[(2*j2+1)*CC + l], we[(2*j2+1)*CC + 32 + l]);
    }
    __syncthreads();
    int n = blockIdx.x * 4 + nloc;
    int beg0 = g_off[n], end0 = g_off[n+1];
    int mid = beg0 + ((end0 - beg0) >> 1);
    int beg = half ? mid : beg0;
    int end = half ? end0 : mid;
    float ad_l = adstp[n*4 + lb];
    float mx0[BB], mx1[BB];
    #pragma unroll
    for (int b = 0; b < BB; b++) { mx0[b] = -CUDART_INF_F; mx1[b] = -CUDART_INF_F; }
    int2 nx = (beg < end) ? __ldg(&g_lst[beg]) : make_int2(0, 0);
    for (int i = beg; i < end; i++) {
        int e = nx.x, src = nx.y;
        if (i + 1 < end) nx = __ldg(&g_lst[i+1]);
        const float4* p4 = (const float4*)(eattr + (size_t)e * CE);
        float4 A = p4[0], B = p4[1], Cv = p4[2], D = p4[3];
        float esc = __ldg(&escp[e]);
        float as_l = __ldg(&asrcp[src*4 + lb]);
        float att_l = sigmoidf(as_l + ad_l + esc);
        float attv[BB];
        #pragma unroll
        for (int b = 0; b < BB; b++) attv[b] = __shfl_sync(0xffffffffu, att_l, b, 4);
        float av[16] = {A.x,A.y,A.z,A.w, B.x,B.y,B.z,B.w, Cv.x,Cv.y,Cv.z,Cv.w, D.x,D.y,D.z,D.w};
        float gx = 0.f, gy = 0.f, hx = 0.f, hy = 0.f;
        #pragma unroll
        for (int j2 = 0; j2 < CE/2; j2++) {
            float4 wv = wsh4[j2*32 + lane];
            gx += av[2*j2]   * wv.x;  gy += av[2*j2]   * wv.y;
            hx += av[2*j2+1] * wv.z;  hy += av[2*j2+1] * wv.w;
        }
        float gA = sigmoidf(gx + hx);
        float gB = sigmoidf(gy + hy);
        // packed xp: 2 x LDG.128 cover 4 batches x 2 channels for this lane
        const float* xb = &xp[src*256 + lane*8];
        float4 f1 = *(const float4*)(xb);       // b0q0 b0q1 b1q0 b1q1
        float4 f2 = *(const float4*)(xb + 4);   // b2q0 b2q1 b3q0 b3q1
        mx0[0] = fmaxf(mx0[0], attv[0] * f1.x * gA);
        mx1[0] = fmaxf(mx1[0], attv[0] * f1.y * gB);
        mx0[1] = fmaxf(mx0[1], attv[1] * f1.z * gA);
        mx1[1] = fmaxf(mx1[1], attv[1] * f1.w * gB);
        mx0[2] = fmaxf(mx0[2], attv[2] * f2.x * gA);
        mx1[2] = fmaxf(mx1[2], attv[2] * f2.y * gB);
        mx0[3] = fmaxf(mx0[3], attv[3] * f2.z * gA);
        mx1[3] = fmaxf(mx1[3], attv[3] * f2.w * gB);
    }
    if (half == 1) {
        #pragma unroll
        for (int b = 0; b < BB; b++) part[nloc][b][lane] = make_float2(mx0[b], mx1[b]);
    }
    __syncthreads();
    if (half == 0) {
        bool empty = (beg0 == end0);
        #pragma unroll
        for (int b = 0; b < BB; b++) {
            float2 p1 = part[nloc][b][lane];
            float2 o = empty ? make_float2(0.f, 0.f)
                             : make_float2(fmaxf(mx0[b], p1.x), fmaxf(mx1[b], p1.y));
            *(float2*)&aggrp[(n*BB + b)*CC + lane*2] = o;
        }
    }
}

// ---------------- launch 4: layer1 output + layer2 transform (67 KB) -------
__global__ void mid_kernel(const float* __restrict__ ow, const float* __restrict__ ob,
                           const float* __restrict__ wn2) {
    extern __shared__ __align__(16) float sm[];
    float* ows  = sm;                  // 2*CC*CC
    float* xs_t = ows + 2*CC*CC;       // CC*XSTRIDE (xp1, later ys)
    float* as_t = xs_t + CC*XSTRIDE;   // CC*XSTRIDE (aggr, later wn2)
    __shared__ float obi[CC], qs[CC], ks_[CC];
    __shared__ float redq[64], redk[64];
    int tid = threadIdx.x;
    for (int i = tid; i < 2*CC*CC; i += 256) {
        int k = i >> 6, c = i & 63;
        int pk = (k < CC) ? ilv(k) : CC + ilv(k - CC);
        ows[pk*CC + ilv(c)] = ow[i];
    }
    if (tid < CC) {
        int c = unilv(tid);
        obi[tid] = ob[c];
        qs[tid]  = g_qaw[1][c];
        ks_[tid] = g_kaw[1][c];
    }
    int row0 = blockIdx.x * 64;
    size_t nbase = (size_t)row0 * CC;   // == node0*256
    for (int i = tid*4; i < 64*CC; i += 1024) {
        {
            float4 v = *(const float4*)&g_xp1[nbase + i];
            int np = i >> 8, l = (i & 255) >> 3, s = (i >> 2) & 1;
            int rb = np*4 + 2*s;
            int p0 = 2*l, p1 = 2*l + 1;
            xs_t[p0*XSTRIDE + rb]     = v.x;
            xs_t[p1*XSTRIDE + rb]     = v.y;
            xs_t[p0*XSTRIDE + rb + 1] = v.z;
            xs_t[p1*XSTRIDE + rb + 1] = v.w;
        }
        {
            float4 u = *(const float4*)&g_aggr[nbase + i];
            int r = i >> 6, p0 = i & 63;
            as_t[(p0+0)*XSTRIDE + r] = u.x;
            as_t[(p0+1)*XSTRIDE + r] = u.y;
            as_t[(p0+2)*XSTRIDE + r] = u.z;
            as_t[(p0+3)*XSTRIDE + r] = u.w;
        }
    }
    __syncthreads();
    int tc = tid & 15, tg = tid >> 4;
    int r0 = tg * 4;
    float acc[4][4];
    {
        float4 bv = *(float4*)&obi[tc*4];
        #pragma unroll
        for (int i = 0; i < 4; i++) { acc[i][0]=bv.x; acc[i][1]=bv.y; acc[i][2]=bv.z; acc[i][3]=bv.w; }
    }
    #pragma unroll 16
    for (int kk = 0; kk < CC; kk++) {
        float4 w = *(float4*)&ows[kk*CC + tc*4];
        float4 a = *(float4*)&xs_t[kk*XSTRIDE + r0];
        acc[0][0]+=a.x*w.x; acc[0][1]+=a.x*w.y; acc[0][2]+=a.x*w.z; acc[0][3]+=a.x*w.w;
        acc[1][0]+=a.y*w.x; acc[1][1]+=a.y*w.y; acc[1][2]+=a.y*w.z; acc[1][3]+=a.y*w.w;
        acc[2][0]+=a.z*w.x; acc[2][1]+=a.z*w.y; acc[2][2]+=a.z*w.z; acc[2][3]+=a.z*w.w;
        acc[3][0]+=a.w*w.x; acc[3][1]+=a.w*w.y; acc[3][2]+=a.w*w.z; acc[3][3]+=a.w*w.w;
    }
    #pragma unroll 16
    for (int kk = 0; kk < CC; kk++) {
        float4 w = *(float4*)&ows[(CC+kk)*CC + tc*4];
        float4 a = *(float4*)&as_t[kk*XSTRIDE + r0];
        acc[0][0]+=a.x*w.x; acc[0][1]+=a.x*w.y; acc[0][2]+=a.x*w.z; acc[0][3]+=a.x*w.w;
        acc[1][0]+=a.y*w.x; acc[1][1]+=a.y*w.y; acc[1][2]+=a.y*w.z; acc[1][3]+=a.y*w.w;
        acc[2][0]+=a.z*w.x; acc[2][1]+=a.z*w.y; acc[2][2]+=a.z*w.z; acc[2][3]+=a.z*w.w;
        acc[3][0]+=a.w*w.x; acc[3][1]+=a.w*w.y; acc[3][2]+=a.w*w.z; acc[3][3]+=a.w*w.w;
    }
    __syncthreads();   // everyone done READING as_t/xs_t for phase 1+2
    // ys -> xs_t in place; wn2 -> as_t region
    #pragma unroll
    for (int i = 0; i < 4; i++) {
        #pragma unroll
        for (int j = 0; j < 4; j++) {
            int p = tc*4 + j, r = r0 + i;
            float v = xs_t[p*XSTRIDE + r] + acc[i][j];
            xs_t[p*XSTRIDE + r] = (v > 0.f) ? v : 0.01f * v;
        }
    }
    for (int i = tid; i < CC*CC; i += 256) {
        int k = i >> 6, c = i & 63;
        as_t[ilv(k)*CC + ilv(c)] = wn2[i];   // reuse as_t as [k][c] weight tile
    }
    __syncthreads();
    float acc2[4][4] = {};
    #pragma unroll 16
    for (int kk = 0; kk < CC; kk++) {
        float4 w = *(float4*)&as_t[kk*CC + tc*4];
        float4 a = *(float4*)&xs_t[kk*XSTRIDE + r0];
        acc2[0][0]+=a.x*w.x; acc2[0][1]+=a.x*w.y; acc2[0][2]+=a.x*w.z; acc2[0][3]+=a.x*w.w;
        acc2[1][0]+=a.y*w.x; acc2[1][1]+=a.y*w.y; acc2[1][2]+=a.y*w.z; acc2[1][3]+=a.y*w.w;
        acc2[2][0]+=a.z*w.x; acc2[2][1]+=a.z*w.y; acc2[2][2]+=a.z*w.z; acc2[2][3]+=a.z*w.w;
        acc2[3][0]+=a.w*w.x; acc2[3][1]+=a.w*w.y; acc2[3][2]+=a.w*w.z; acc2[3][3]+=a.w*w.w;
    }
    // packed xp2 write
    {
        int node = (row0 >> 2) + tg;
        int l0 = tc * 2;
        float* base = &g_xp2[node*256 + l0*8];
        *(float4*)(base + 0)  = make_float4(acc2[0][0], acc2[0][1], acc2[1][0], acc2[1][1]);
        *(float4*)(base + 4)  = make_float4(acc2[2][0], acc2[2][1], acc2[3][0], acc2[3][1]);
        *(float4*)(base + 8)  = make_float4(acc2[0][2], acc2[0][3], acc2[1][2], acc2[1][3]);
        *(float4*)(base + 12) = make_float4(acc2[2][2], acc2[2][3], acc2[3][2], acc2[3][3]);
    }
    float4 qv = *(float4*)&qs[tc*4];
    float4 kv = *(float4*)&ks_[tc*4];
    #pragma unroll
    for (int i = 0; i < 4; i++) {
        float pq = acc2[i][0]*qv.x + acc2[i][1]*qv.y + acc2[i][2]*qv.z + acc2[i][3]*qv.w;
        float pk = acc2[i][0]*kv.x + acc2[i][1]*kv.y + acc2[i][2]*kv.z + acc2[i][3]*kv.w;
        #pragma unroll
        for (int o = 8; o; o >>= 1) {
            pq += __shfl_down_sync(0xffffffffu, pq, o, 16);
            pk += __shfl_down_sync(0xffffffffu, pk, o, 16);
        }
        if (tc == 0) { redq[tg*4 + i] = pq; redk[tg*4 + i] = pk; }
    }
    __syncthreads();
    if (tid < 64) {
        g_asrc2[row0 + tid] = redq[tid];
        g_adst2[row0 + tid] = redk[tid];
    }
}

// ---------------- launch 6: final output + re-zero degrees -----------------
__global__ void out2_kernel(const float* __restrict__ ow, const float* __restrict__ ob,
                            float* __restrict__ yout) {
    extern __shared__ __align__(16) float sm[];
    float* ows  = sm;
    float* xs_t = ows + 2*CC*CC;
    float* as_t = xs_t + CC*XSTRIDE;
    __shared__ float obi[CC];
    int tid = threadIdx.x;
    if (blockIdx.x < 40) {
        int i = blockIdx.x * 256 + tid;
        if (i < NN) g_deg[i] = 0;
    }
    for (int i = tid; i < 2*CC*CC; i += 256) {
        int k = i >> 6, c = i & 63;
        int pk = (k < CC) ? ilv(k) : CC + ilv(k - CC);
        ows[pk*CC + ilv(c)] = ow[i];
    }
    if (tid < CC) obi[tid] = ob[unilv(tid)];
    int row0 = blockIdx.x * 64;
    size_t nbase = (size_t)row0 * CC;
    for (int i = tid*4; i < 64*CC; i += 1024) {
        {   // xp2 packed
            float4 v = *(const float4*)&g_xp2[nbase + i];
            int np = i >> 8, l = (i & 255) >> 3, s = (i >> 2) & 1;
            int rb = np*4 + 2*s;
            int p0 = 2*l, p1 = 2*l + 1;
            xs_t[p0*XSTRIDE + rb]     = v.x;
            xs_t[p1*XSTRIDE + rb]     = v.y;
            xs_t[p0*XSTRIDE + rb + 1] = v.z;
            xs_t[p1*XSTRIDE + rb + 1] = v.w;
        }
        {   // aggr interleaved
            float4 u = *(const float4*)&g_aggr[nbase + i];
            int r = i >> 6, p0 = i & 63;
            as_t[(p0+0)*XSTRIDE + r] = u.x;
            as_t[(p0+1)*XSTRIDE + r] = u.y;
            as_t[(p0+2)*XSTRIDE + r] = u.z;
            as_t[(p0+3)*XSTRIDE + r] = u.w;
        }
    }
    __syncthreads();
    int tc = tid & 15, tg = tid >> 4;
    int r0 = tg * 4;
    float acc[4][4];
    {
        float4 bv = *(float4*)&obi[tc*4];
        #pragma unroll
        for (int i = 0; i < 4; i++) { acc[i][0]=bv.x; acc[i][1]=bv.y; acc[i][2]=bv.z; acc[i][3]=bv.w; }
    }
    #pragma unroll 16
    for (int kk = 0; kk < CC; kk++) {
        float4 w = *(float4*)&ows[kk*CC + tc*4];
        float4 a = *(float4*)&xs_t[kk*XSTRIDE + r0];
        acc[0][0]+=a.x*w.x; acc[0][1]+=a.x*w.y; acc[0][2]+=a.x*w.z; acc[0][3]+=a.x*w.w;
        acc[1][0]+=a.y*w.x; acc[1][1]+=a.y*w.y; acc[1][2]+=a.y*w.z; acc[1][3]+=a.y*w.w;
        acc[2][0]+=a.z*w.x; acc[2][1]+=a.z*w.y; acc[2][2]+=a.z*w.z; acc[2][3]+=a.z*w.w;
        acc[3][0]+=a.w*w.x; acc[3][1]+=a.w*w.y; acc[3][2]+=a.w*w.z; acc[3][3]+=a.w*w.w;
    }
    #pragma unroll 16
    for (int kk = 0; kk < CC; kk++) {
        float4 w = *(float4*)&ows[(CC+kk)*CC + tc*4];
        float4 a = *(float4*)&as_t[kk*XSTRIDE + r0];
        acc[0][0]+=a.x*w.x; acc[0][1]+=a.x*w.y; acc[0][2]+=a.x*w.z; acc[0][3]+=a.x*w.w;
        acc[1][0]+=a.y*w.x; acc[1][1]+=a.y*w.y; acc[1][2]+=a.y*w.z; acc[1][3]+=a.y*w.w;
        acc[2][0]+=a.z*w.x; acc[2][1]+=a.z*w.y; acc[2][2]+=a.z*w.z; acc[2][3]+=a.z*w.w;
        acc[3][0]+=a.w*w.x; acc[3][1]+=a.w*w.y; acc[3][2]+=a.w*w.z; acc[3][3]+=a.w*w.w;
    }
    #pragma unroll
    for (int i = 0; i < 4; i++) {
        int row = row0 + r0 + i;
        #pragma unroll
        for (int j = 0; j < 4; j++) {
            int p = tc*4 + j;
            float v = xs_t[p*XSTRIDE + (r0+i)] + acc[i][j];
            yout[row*CC + unilv(p)] = (v > 0.f) ? v : 0.01f * v;
        }
    }
}

// ---------------- host orchestration ----------------------------------------
extern "C" void kernel_launch(void* const* d_in, const int* in_sizes, int n_in,
                              void* d_out, int out_size) {
    const float* X   = (const float*)d_in[0];
    const int*   ei  = (const int*)  d_in[1];
    const float* ea  = (const float*)d_in[2];
    const float* wn1 = (const float*)d_in[3];
    const float* we1 = (const float*)d_in[4];
    const float* q1  = (const float*)d_in[5];
    const float* k1  = (const float*)d_in[6];
    const float* aw1 = (const float*)d_in[7];
    const float* ab1 = (const float*)d_in[8];
    const float* ow1 = (const float*)d_in[9];
    const float* ob1 = (const float*)d_in[10];
    const float* wn2 = (const float*)d_in[11];
    const float* we2 = (const float*)d_in[12];
    const float* q2  = (const float*)d_in[13];
    const float* k2  = (const float*)d_in[14];
    const float* aw2 = (const float*)d_in[15];
    const float* ab2 = (const float*)d_in[16];
    const float* ow2 = (const float*)d_in[17];
    const float* ob2 = (const float*)d_in[18];

    float *xp1, *xp2, *asrc1, *adst1, *asrc2, *adst2, *aggr;
    float *esc1, *esc2;
    cudaGetSymbolAddress((void**)&xp1,   g_xp1);
    cudaGetSymbolAddress((void**)&xp2,   g_xp2);
    cudaGetSymbolAddress((void**)&asrc1, g_asrc1);
    cudaGetSymbolAddress((void**)&adst1, g_adst1);
    cudaGetSymbolAddress((void**)&asrc2, g_asrc2);
    cudaGetSymbolAddress((void**)&adst2, g_adst2);
    cudaGetSymbolAddress((void**)&aggr,  g_aggr);
    cudaGetSymbolAddress((void**)&esc1,  g_esc1);
    cudaGetSymbolAddress((void**)&esc2,  g_esc2);

    const int MID_SMEM = (2*CC*CC + 2*CC*XSTRIDE) * 4;   // ~67 KB
    const int OUT_SMEM = (2*CC*CC + 2*CC*XSTRIDE) * 4;   // ~67 KB
    static bool attr_done = false;
    if (!attr_done) {
        cudaFuncSetAttribute(mid_kernel,  cudaFuncAttributeMaxDynamicSharedMemorySize, MID_SMEM);
        cudaFuncSetAttribute(out2_kernel, cudaFuncAttributeMaxDynamicSharedMemorySize, OUT_SMEM);
        attr_done = true;
    }

    prep_count_kernel<<<625, 256>>>(ei, q1, k1, aw1, ab1, we1, q2, k2, aw2, ab2, we2); // 0
    scan_kernel<<<1, 1024>>>();                                                        // 1
    xform1_scatter_kernel<<<625, 256>>>(X, wn1, ei, ea);                               // 2
    aggr_kernel<<<NN/4, 256>>>(xp1, asrc1, adst1, aggr, we1, ea, esc1);                // 3 <- probe
    mid_kernel<<<NR/64, 256, MID_SMEM>>>(ow1, ob1, wn2);                               // 4
    aggr_kernel<<<NN/4, 256>>>(xp2, asrc2, adst2, aggr, we2, ea, esc2);                // 5
    out2_kernel<<<NR/64, 256, OUT_SMEM>>>(ow2, ob2, (float*)d_out);                    // 6
}